// round 7
// baseline (speedup 1.0000x reference)
#include <cuda_runtime.h>
#include <cstdint>

#define N_NODES    100000
#define EMB_DIM    128
#define BATCH      16384
#define NUM_SAMPLE 25

#define VEC_PER_ROW (EMB_DIM / 4)   // 32 float4 per row

// One warp handles TWO rows (interleaved streams). 1024 blocks x 8 warps = 8192
// warps = exactly 16384 rows; zero tail, doubled per-warp MLP.
#define BLOCK_THREADS 256
#define GRID_BLOCKS   (BATCH / 2 / (BLOCK_THREADS / 32))   // 1024

__global__ __launch_bounds__(BLOCK_THREADS) void mean_agg_kernel(
    const float4* __restrict__ emb,      // [N_NODES, 32] as float4
    const int* __restrict__ neigh,       // [BATCH, NUM_SAMPLE], int32
    float4* __restrict__ out)            // [BATCH, 32] as float4
{
    const int warp_id = (blockIdx.x * BLOCK_THREADS + threadIdx.x) >> 5;
    const int lane    = threadIdx.x & 31;

    const int row0 = warp_id * 2;
    const int row1 = row0 + 1;

    // Lane l (< 25) holds sample l's index for each of the two rows.
    const int* nb0 = neigh + row0 * NUM_SAMPLE;
    const int* nb1 = neigh + row1 * NUM_SAMPLE;
    int idx0 = (lane < NUM_SAMPLE) ? nb0[lane] : 0;
    int idx1 = (lane < NUM_SAMPLE) ? nb1[lane] : 0;

    float4 acc0 = make_float4(0.f, 0.f, 0.f, 0.f);
    float4 acc1 = make_float4(0.f, 0.f, 0.f, 0.f);

    #pragma unroll
    for (int s = 0; s < NUM_SAMPLE; ++s) {
        int id0 = __shfl_sync(0xffffffffu, idx0, s);
        int id1 = __shfl_sync(0xffffffffu, idx1, s);
        // Two independent gather streams -> back-to-back LDG.E.128 issues,
        // doubling per-warp loads in flight vs the single-row version.
        float4 v0 = __ldg(&emb[(unsigned)id0 * VEC_PER_ROW + lane]);
        float4 v1 = __ldg(&emb[(unsigned)id1 * VEC_PER_ROW + lane]);
        acc0.x += v0.x; acc0.y += v0.y; acc0.z += v0.z; acc0.w += v0.w;
        acc1.x += v1.x; acc1.y += v1.y; acc1.z += v1.z; acc1.w += v1.w;
    }

    const float inv = 1.0f / (float)NUM_SAMPLE;   // 0.04
    acc0.x *= inv; acc0.y *= inv; acc0.z *= inv; acc0.w *= inv;
    acc1.x *= inv; acc1.y *= inv; acc1.z *= inv; acc1.w *= inv;

    out[(unsigned)row0 * VEC_PER_ROW + lane] = acc0;
    out[(unsigned)row1 * VEC_PER_ROW + lane] = acc1;
}

extern "C" void kernel_launch(void* const* d_in, const int* in_sizes, int n_in,
                              void* d_out, int out_size)
{
    const float4* emb   = (const float4*)d_in[0];
    const int*    neigh = (const int*)d_in[1];
    float4*       out   = (float4*)d_out;

    mean_agg_kernel<<<GRID_BLOCKS, BLOCK_THREADS>>>(emb, neigh, out);
}

// round 8
// speedup vs baseline: 1.1366x; 1.1366x over previous
#include <cuda_runtime.h>
#include <cstdint>

#define N_NODES    100000
#define EMB_DIM    128
#define BATCH      16384
#define NUM_SAMPLE 25

#define VEC_PER_ROW (EMB_DIM / 4)   // 32 float4 per row

// R3-proven shape (1 warp per row, 16384 warps total) with finer block grain:
// 4096 blocks x 128 threads (4 warps/block) for smoother tail-wave packing.
#define BLOCK_THREADS 128
#define GRID_BLOCKS   (BATCH / (BLOCK_THREADS / 32))   // 4096

__global__ __launch_bounds__(BLOCK_THREADS) void mean_agg_kernel(
    const float4* __restrict__ emb,      // [N_NODES, 32] as float4
    const int* __restrict__ neigh,       // [BATCH, NUM_SAMPLE], int32
    float4* __restrict__ out)            // [BATCH, 32] as float4
{
    const int warp_id = (blockIdx.x * BLOCK_THREADS + threadIdx.x) >> 5;
    const int lane    = threadIdx.x & 31;

    // Lane l (< 25) holds sample l's neighbor index for this row.
    const int* nb = neigh + warp_id * NUM_SAMPLE;
    int my_idx = (lane < NUM_SAMPLE) ? nb[lane] : 0;

    float4 acc = make_float4(0.f, 0.f, 0.f, 0.f);

    #pragma unroll
    for (int s = 0; s < NUM_SAMPLE; ++s) {
        int id = __shfl_sync(0xffffffffu, my_idx, s);
        float4 v = __ldg(&emb[(unsigned)id * VEC_PER_ROW + lane]);
        acc.x += v.x;
        acc.y += v.y;
        acc.z += v.z;
        acc.w += v.w;
    }

    const float inv = 1.0f / (float)NUM_SAMPLE;   // 0.04
    acc.x *= inv; acc.y *= inv; acc.z *= inv; acc.w *= inv;

    out[(unsigned)warp_id * VEC_PER_ROW + lane] = acc;
}

extern "C" void kernel_launch(void* const* d_in, const int* in_sizes, int n_in,
                              void* d_out, int out_size)
{
    const float4* emb   = (const float4*)d_in[0];
    const int*    neigh = (const int*)d_in[1];
    float4*       out   = (float4*)d_out;

    mean_agg_kernel<<<GRID_BLOCKS, BLOCK_THREADS>>>(emb, neigh, out);
}